// round 8
// baseline (speedup 1.0000x reference)
#include <cuda_runtime.h>
#include <math.h>

#define BB   8
#define NN   4096
#define TPB  256
#define QPT  8                     // queries per thread
#define QPB  (TPB * QPT)           // 2048 queries per block
#define NQCH (NN / QPB)            // 2 query chunks
#define NTCH 8                     // target chunks
#define TGT_PER_BLK (NN / NTCH)    // 512 targets per block
#define TILE_P (TGT_PER_BLK / 2)   // 256 packed target-pairs (8 KB smem)
#define PSTEPS (NN / 2)            // 2048 packed pairs per (dir,b)
#define NRED_BLK 64                // reduce-kernel blocks
#define QTOT (2 * BB * NN)         // 65536 query-min slots

typedef unsigned long long ull;

// Scratch (__device__ globals; allocation forbidden)
__device__ float4 g_xy[2][BB][PSTEPS];   // (x0,x1,y0,y1) packed target pairs
__device__ float4 g_zh[2][BB][PSTEPS];   // (z0,z1,h0,h1), h = 0.5*|p|^2
__device__ float4 g_q [2][BB][NN];       // AoS queries (x,y,z,h)
__device__ float  g_h [2][BB][NN];       // query half-norms (flat for reduce)
__device__ unsigned int g_minenc[QTOT];  // order-encoded per-query mins
__device__ float  g_partials[NRED_BLK];
__device__ unsigned int g_count = 0;

// ---- packed f32x2 helpers (sm_103a) --------------------------------------
__device__ __forceinline__ ull fma2(ull a, ull b, ull c) {
    ull d;
    asm("fma.rn.f32x2 %0, %1, %2, %3;" : "=l"(d) : "l"(a), "l"(b), "l"(c));
    return d;
}
__device__ __forceinline__ ull pack2(float lo, float hi) {
    ull r;
    asm("mov.b64 %0, {%1, %2};" : "=l"(r) : "f"(lo), "f"(hi));
    return r;
}
__device__ __forceinline__ void unpack2(ull v, float& lo, float& hi) {
    asm("mov.b64 {%0, %1}, %2;" : "=f"(lo), "=f"(hi) : "l"(v));
}
// order-preserving float<->uint encode (no NaNs in this workload)
__device__ __forceinline__ unsigned int enc_f(float f) {
    unsigned int u = __float_as_uint(f);
    return ((int)u >= 0) ? (u ^ 0x80000000u) : ~u;
}
__device__ __forceinline__ float dec_f(unsigned int k) {
    return (k & 0x80000000u) ? __uint_as_float(k ^ 0x80000000u)
                             : __uint_as_float(~k);
}

// ---------------------------------------------------------------------------
// Kernel 1: rel transforms + loss_trans + point transform, coalesced smem
//           staging of model_points + minenc init. (proven, ~5.8us)
// ---------------------------------------------------------------------------
__global__ void __launch_bounds__(TPB) k_prep(
    const float* __restrict__ pred_rot,   const float* __restrict__ pred_trans,
    const float* __restrict__ ctx_hyp_rot,const float* __restrict__ ctx_hyp_trans,
    const float* __restrict__ gt_rot,     const float* __restrict__ gt_trans,
    const float* __restrict__ ctx_gt_rot, const float* __restrict__ ctx_gt_trans,
    const float* __restrict__ mp,         float* __restrict__ out)
{
    __shared__ float sR[2][BB][9];
    __shared__ float sT[2][BB][3];
    __shared__ float s_mp[TPB * 3];

    const int tid = threadIdx.x;
    if (tid < 2 * BB) {
        const int w = tid / BB, b = tid % BB;
        const float* Ra = (w == 0 ? pred_rot      : gt_rot)       + b * 9;
        const float* ta = (w == 0 ? pred_trans    : gt_trans)     + b * 3;
        const float* Rb = (w == 0 ? ctx_hyp_rot   : ctx_gt_rot)   + b * 9;
        const float* tb = (w == 0 ? ctx_hyp_trans : ctx_gt_trans) + b * 3;
        #pragma unroll
        for (int i = 0; i < 3; i++)
            #pragma unroll
            for (int k = 0; k < 3; k++) {
                float s = 0.f;
                #pragma unroll
                for (int j = 0; j < 3; j++) s += Ra[i*3+j] * Rb[k*3+j];
                sR[w][b][i*3+k] = s;
            }
        #pragma unroll
        for (int i = 0; i < 3; i++) {
            float s = ta[i];
            #pragma unroll
            for (int j = 0; j < 3; j++) s -= sR[w][b][i*3+j] * tb[j];
            sT[w][b][i] = s;
        }
    }

    {
        const float* src = mp + blockIdx.x * (TPB * 3);
        #pragma unroll
        for (int i = tid; i < TPB * 3; i += TPB) s_mp[i] = src[i];
    }
    __syncthreads();

    if (blockIdx.x == 0 && tid == 0) {
        float s = 0.f;
        for (int b = 0; b < BB; b++)
            for (int i = 0; i < 3; i++)
                s += fabsf(sT[0][b][i] - sT[1][b][i]);
        out[1] = s * (1.0f / (BB * 3));
    }

    const int gpt = blockIdx.x * TPB + tid;   // global point index < BB*NN
    g_minenc[gpt]           = 0xFFFFFFFFu;
    g_minenc[gpt + BB * NN] = 0xFFFFFFFFu;

    const int b    = gpt >> 12;
    const int n    = gpt & (NN - 1);
    const int pair = n >> 1;
    const int lane = n & 1;
    const float px = s_mp[tid * 3 + 0];
    const float py = s_mp[tid * 3 + 1];
    const float pz = s_mp[tid * 3 + 2];

    #pragma unroll
    for (int w = 0; w < 2; w++) {
        const float* R = sR[w][b];
        const float* t = sT[w][b];
        float x = fmaf(R[0], px, fmaf(R[1], py, fmaf(R[2], pz, t[0])));
        float y = fmaf(R[3], px, fmaf(R[4], py, fmaf(R[5], pz, t[1])));
        float z = fmaf(R[6], px, fmaf(R[7], py, fmaf(R[8], pz, t[2])));
        float h = 0.5f * fmaf(x, x, fmaf(y, y, z * z));
        float* xy = (float*)&g_xy[w][b][pair];
        float* zh = (float*)&g_zh[w][b][pair];
        xy[lane]     = x;  xy[2 + lane] = y;
        zh[lane]     = z;  zh[2 + lane] = h;
        g_q[w][b][n] = make_float4(x, y, z, h);
        g_h[w][b][n] = h;
    }
}

// ---------------------------------------------------------------------------
// Deterministic block sum reduction (valid in thread 0)
// ---------------------------------------------------------------------------
__device__ __forceinline__ float block_reduce_sum(float v)
{
    __shared__ float ws[TPB / 32];
    #pragma unroll
    for (int o = 16; o > 0; o >>= 1) v += __shfl_down_sync(0xffffffffu, v, o);
    if ((threadIdx.x & 31) == 0) ws[threadIdx.x >> 5] = v;
    __syncthreads();
    if (threadIdx.x < 32) {
        v = (threadIdx.x < TPB / 32) ? ws[threadIdx.x] : 0.f;
        #pragma unroll
        for (int o = 4; o > 0; o >>= 1) v += __shfl_down_sync(0xffffffffu, v, o);
    }
    return v;
}

// ---------------------------------------------------------------------------
// Kernel 2: chamfer partial mins. grid (NQCH=2, BB, 2*NTCH=16) = 256 blocks,
// 256 thr, QPT=8: each j-iter's 2x LDS.128 (smem crossbar, the measured
// bottleneck at QPT=4) now amortized over 8 queries -> FMA-pipe bound.
// __launch_bounds__(TPB, 2): 128-reg budget, kills the regs=40 spill cliff.
// ---------------------------------------------------------------------------
__global__ void __launch_bounds__(TPB, 2) k_chamfer()
{
    __shared__ float4 s_xy[TILE_P];
    __shared__ float4 s_zh[TILE_P];

    const int dir = blockIdx.z >> 3;
    const int tc  = blockIdx.z & 7;
    const int b   = blockIdx.y;
    const int tid = threadIdx.x;

    // load target tile (512 targets = 256 packed pairs, 8 KB)
    {
        const float4* __restrict__ gxy = &g_xy[1 - dir][b][tc * TILE_P];
        const float4* __restrict__ gzh = &g_zh[1 - dir][b][tc * TILE_P];
        s_xy[tid] = gxy[tid];
        s_zh[tid] = gzh[tid];
    }

    // load 8 queries, pre-negated + packed (kept register-resident)
    const int nbase = blockIdx.x * QPB + tid;
    ull nx[QPT], ny[QPT], nz[QPT];
    #pragma unroll
    for (int k = 0; k < QPT; k++) {
        float4 q = g_q[dir][b][nbase + k * TPB];
        nx[k] = pack2(-q.x, -q.x);
        ny[k] = pack2(-q.y, -q.y);
        nz[k] = pack2(-q.z, -q.z);
    }

    float ma[QPT], mb[QPT];
    #pragma unroll
    for (int k = 0; k < QPT; k++) { ma[k] = INFINITY; mb[k] = INFINITY; }

    __syncthreads();

    const ulonglong2* __restrict__ axy = (const ulonglong2*)s_xy;
    const ulonglong2* __restrict__ azh = (const ulonglong2*)s_zh;

    #pragma unroll 4
    for (int j = 0; j < TILE_P; j++) {
        const ulonglong2 A = axy[j];   // (x0,x1) (y0,y1)
        const ulonglong2 B = azh[j];   // (z0,z1) (h0,h1)
        #pragma unroll
        for (int k = 0; k < QPT; k++) {
            ull v = fma2(nz[k], B.x, B.y);
            v = fma2(ny[k], A.y, v);
            v = fma2(nx[k], A.x, v);
            float lo, hi;
            unpack2(v, lo, hi);
            ma[k] = fminf(ma[k], lo);
            mb[k] = fminf(mb[k], hi);
        }
    }

    #pragma unroll
    for (int k = 0; k < QPT; k++) {
        const unsigned int key = enc_f(fminf(ma[k], mb[k]));
        atomicMin(&g_minenc[(dir * BB + b) * NN + nbase + k * TPB], key);
    }
}

// ---------------------------------------------------------------------------
// Kernel 3: decode mins, deferred sqrt, global sum -> loss_geo.
// ---------------------------------------------------------------------------
__global__ void __launch_bounds__(TPB) k_reduce(float* __restrict__ out)
{
    const int tid  = threadIdx.x;
    const int base = blockIdx.x * (QTOT / NRED_BLK) + tid;   // 1024 per block
    const float* __restrict__ hflat = &g_h[0][0][0];

    float s = 0.f;
    #pragma unroll
    for (int k = 0; k < 4; k++) {
        const int q = base + k * TPB;
        const float m = dec_f(g_minenc[q]);
        const float h = hflat[q];
        s += sqrtf(fmaxf(2.0f * (m + h), 0.0f));
    }

    float bs = block_reduce_sum(s);

    __shared__ bool is_last;
    if (tid == 0) {
        g_partials[blockIdx.x] = bs;
        __threadfence();
        is_last = (atomicAdd(&g_count, 1u) == NRED_BLK - 1);
    }
    __syncthreads();

    if (is_last) {
        const volatile float* vp = g_partials;
        float v = (tid < NRED_BLK) ? vp[tid] : 0.f;
        float tot = block_reduce_sum(v);
        if (tid == 0) {
            out[0] = tot * (1.0f / (BB * NN));
            g_count = 0;   // reset for next graph replay
        }
    }
}

// ---------------------------------------------------------------------------
extern "C" void kernel_launch(void* const* d_in, const int* in_sizes, int n_in,
                              void* d_out, int out_size)
{
    const float* pred_rot      = (const float*)d_in[0];
    const float* pred_trans    = (const float*)d_in[1];
    const float* ctx_hyp_rot   = (const float*)d_in[2];
    const float* ctx_hyp_trans = (const float*)d_in[3];
    const float* gt_rot        = (const float*)d_in[4];
    const float* gt_trans      = (const float*)d_in[5];
    const float* ctx_gt_rot    = (const float*)d_in[6];
    const float* ctx_gt_trans  = (const float*)d_in[7];
    const float* model_points  = (const float*)d_in[8];
    float* out = (float*)d_out;

    k_prep<<<(BB * NN) / TPB, TPB>>>(pred_rot, pred_trans,
                                     ctx_hyp_rot, ctx_hyp_trans,
                                     gt_rot, gt_trans,
                                     ctx_gt_rot, ctx_gt_trans,
                                     model_points, out);
    k_chamfer<<<dim3(NQCH, BB, 2 * NTCH), TPB>>>();
    k_reduce<<<NRED_BLK, TPB>>>(out);
}

// round 9
// speedup vs baseline: 1.0074x; 1.0074x over previous
#include <cuda_runtime.h>
#include <math.h>

#define BB   8
#define NN   4096
#define TPB  256
#define QPT  4                     // queries per thread
#define QPB  (TPB * QPT)           // 1024 queries per block
#define NQCH (NN / QPB)            // 4 query chunks
#define NTCH 8                     // target chunks
#define TGT_PER_BLK (NN / NTCH)    // 512 targets per block
#define TILE_P (TGT_PER_BLK / 2)   // 256 packed target-pairs (8 KB smem)
#define PSTEPS (NN / 2)            // 2048 packed pairs per (dir,b)
#define NRED_BLK 64                // reduce-kernel blocks
#define QTOT (2 * BB * NN)         // 65536 query-min slots

typedef unsigned long long ull;

// Scratch (__device__ globals; allocation forbidden)
__device__ float4 g_xy[2][BB][PSTEPS];   // (x0,x1,y0,y1) packed target pairs
__device__ float4 g_zh[2][BB][PSTEPS];   // (z0,z1,h0,h1), h = 0.5*|p|^2
__device__ float4 g_q [2][BB][NN];       // AoS queries (x,y,z,h)
__device__ float  g_h [2][BB][NN];       // query half-norms (flat for reduce)
__device__ unsigned int g_minenc[QTOT];  // order-encoded per-query mins
__device__ float  g_partials[NRED_BLK];
__device__ unsigned int g_count = 0;

// ---- packed f32x2 helpers (sm_103a) --------------------------------------
__device__ __forceinline__ ull fma2(ull a, ull b, ull c) {
    ull d;
    asm("fma.rn.f32x2 %0, %1, %2, %3;" : "=l"(d) : "l"(a), "l"(b), "l"(c));
    return d;
}
__device__ __forceinline__ ull pack2(float lo, float hi) {
    ull r;
    asm("mov.b64 %0, {%1, %2};" : "=l"(r) : "f"(lo), "f"(hi));
    return r;
}
__device__ __forceinline__ void unpack2(ull v, float& lo, float& hi) {
    asm("mov.b64 {%0, %1}, %2;" : "=f"(lo), "=f"(hi) : "l"(v));
}
// order-preserving float<->uint encode (no NaNs in this workload)
__device__ __forceinline__ unsigned int enc_f(float f) {
    unsigned int u = __float_as_uint(f);
    return ((int)u >= 0) ? (u ^ 0x80000000u) : ~u;
}
__device__ __forceinline__ float dec_f(unsigned int k) {
    return (k & 0x80000000u) ? __uint_as_float(k ^ 0x80000000u)
                             : __uint_as_float(~k);
}

// ---------------------------------------------------------------------------
// Kernel 1: rel transforms + loss_trans + point transform, coalesced smem
//           staging of model_points + minenc init. (proven, ~5.8us)
// ---------------------------------------------------------------------------
__global__ void __launch_bounds__(TPB) k_prep(
    const float* __restrict__ pred_rot,   const float* __restrict__ pred_trans,
    const float* __restrict__ ctx_hyp_rot,const float* __restrict__ ctx_hyp_trans,
    const float* __restrict__ gt_rot,     const float* __restrict__ gt_trans,
    const float* __restrict__ ctx_gt_rot, const float* __restrict__ ctx_gt_trans,
    const float* __restrict__ mp,         float* __restrict__ out)
{
    __shared__ float sR[2][BB][9];
    __shared__ float sT[2][BB][3];
    __shared__ float s_mp[TPB * 3];

    const int tid = threadIdx.x;
    if (tid < 2 * BB) {
        const int w = tid / BB, b = tid % BB;
        const float* Ra = (w == 0 ? pred_rot      : gt_rot)       + b * 9;
        const float* ta = (w == 0 ? pred_trans    : gt_trans)     + b * 3;
        const float* Rb = (w == 0 ? ctx_hyp_rot   : ctx_gt_rot)   + b * 9;
        const float* tb = (w == 0 ? ctx_hyp_trans : ctx_gt_trans) + b * 3;
        #pragma unroll
        for (int i = 0; i < 3; i++)
            #pragma unroll
            for (int k = 0; k < 3; k++) {
                float s = 0.f;
                #pragma unroll
                for (int j = 0; j < 3; j++) s += Ra[i*3+j] * Rb[k*3+j];
                sR[w][b][i*3+k] = s;
            }
        #pragma unroll
        for (int i = 0; i < 3; i++) {
            float s = ta[i];
            #pragma unroll
            for (int j = 0; j < 3; j++) s -= sR[w][b][i*3+j] * tb[j];
            sT[w][b][i] = s;
        }
    }

    {
        const float* src = mp + blockIdx.x * (TPB * 3);
        #pragma unroll
        for (int i = tid; i < TPB * 3; i += TPB) s_mp[i] = src[i];
    }
    __syncthreads();

    if (blockIdx.x == 0 && tid == 0) {
        float s = 0.f;
        for (int b = 0; b < BB; b++)
            for (int i = 0; i < 3; i++)
                s += fabsf(sT[0][b][i] - sT[1][b][i]);
        out[1] = s * (1.0f / (BB * 3));
    }

    const int gpt = blockIdx.x * TPB + tid;   // global point index < BB*NN
    g_minenc[gpt]           = 0xFFFFFFFFu;
    g_minenc[gpt + BB * NN] = 0xFFFFFFFFu;

    const int b    = gpt >> 12;
    const int n    = gpt & (NN - 1);
    const int pair = n >> 1;
    const int lane = n & 1;
    const float px = s_mp[tid * 3 + 0];
    const float py = s_mp[tid * 3 + 1];
    const float pz = s_mp[tid * 3 + 2];

    #pragma unroll
    for (int w = 0; w < 2; w++) {
        const float* R = sR[w][b];
        const float* t = sT[w][b];
        float x = fmaf(R[0], px, fmaf(R[1], py, fmaf(R[2], pz, t[0])));
        float y = fmaf(R[3], px, fmaf(R[4], py, fmaf(R[5], pz, t[1])));
        float z = fmaf(R[6], px, fmaf(R[7], py, fmaf(R[8], pz, t[2])));
        float h = 0.5f * fmaf(x, x, fmaf(y, y, z * z));
        float* xy = (float*)&g_xy[w][b][pair];
        float* zh = (float*)&g_zh[w][b][pair];
        xy[lane]     = x;  xy[2 + lane] = y;
        zh[lane]     = z;  zh[2 + lane] = h;
        g_q[w][b][n] = make_float4(x, y, z, h);
        g_h[w][b][n] = h;
    }
}

// ---------------------------------------------------------------------------
// Deterministic block sum reduction (valid in thread 0)
// ---------------------------------------------------------------------------
__device__ __forceinline__ float block_reduce_sum(float v)
{
    __shared__ float ws[TPB / 32];
    #pragma unroll
    for (int o = 16; o > 0; o >>= 1) v += __shfl_down_sync(0xffffffffu, v, o);
    if ((threadIdx.x & 31) == 0) ws[threadIdx.x >> 5] = v;
    __syncthreads();
    if (threadIdx.x < 32) {
        v = (threadIdx.x < TPB / 32) ? ws[threadIdx.x] : 0.f;
        #pragma unroll
        for (int o = 4; o > 0; o >>= 1) v += __shfl_down_sync(0xffffffffu, v, o);
    }
    return v;
}

// ---------------------------------------------------------------------------
// Kernel 2: chamfer partial mins. grid (NQCH=4, BB, 2*NTCH=16) = 512 blocks,
// 256 thr, QPT=4, 8KB tile. __launch_bounds__(TPB, 4): 4 blocks/SM resident
// (32 warps/SM, 8/SMSP -> doubles latency hiding vs the 2-block configs that
// all plateaued at ~50% issue), 64-reg cap fits the ~55-reg QPT=4 live set.
// Single wave: 512 blocks <= 592 residency slots.
// ---------------------------------------------------------------------------
__global__ void __launch_bounds__(TPB, 4) k_chamfer()
{
    __shared__ float4 s_xy[TILE_P];
    __shared__ float4 s_zh[TILE_P];

    const int dir = blockIdx.z >> 3;
    const int tc  = blockIdx.z & 7;
    const int b   = blockIdx.y;
    const int tid = threadIdx.x;

    // load target tile (512 targets = 256 packed pairs, 8 KB)
    {
        const float4* __restrict__ gxy = &g_xy[1 - dir][b][tc * TILE_P];
        const float4* __restrict__ gzh = &g_zh[1 - dir][b][tc * TILE_P];
        s_xy[tid] = gxy[tid];
        s_zh[tid] = gzh[tid];
    }

    // load 4 queries, pre-negated + packed (register-resident)
    const int nbase = blockIdx.x * QPB + tid;
    ull nx[QPT], ny[QPT], nz[QPT];
    #pragma unroll
    for (int k = 0; k < QPT; k++) {
        float4 q = g_q[dir][b][nbase + k * TPB];
        nx[k] = pack2(-q.x, -q.x);
        ny[k] = pack2(-q.y, -q.y);
        nz[k] = pack2(-q.z, -q.z);
    }

    float ma[QPT], mb[QPT];
    #pragma unroll
    for (int k = 0; k < QPT; k++) { ma[k] = INFINITY; mb[k] = INFINITY; }

    __syncthreads();

    const ulonglong2* __restrict__ axy = (const ulonglong2*)s_xy;
    const ulonglong2* __restrict__ azh = (const ulonglong2*)s_zh;

    #pragma unroll 4
    for (int j = 0; j < TILE_P; j++) {
        const ulonglong2 A = axy[j];   // (x0,x1) (y0,y1)
        const ulonglong2 B = azh[j];   // (z0,z1) (h0,h1)
        #pragma unroll
        for (int k = 0; k < QPT; k++) {
            ull v = fma2(nz[k], B.x, B.y);
            v = fma2(ny[k], A.y, v);
            v = fma2(nx[k], A.x, v);
            float lo, hi;
            unpack2(v, lo, hi);
            ma[k] = fminf(ma[k], lo);
            mb[k] = fminf(mb[k], hi);
        }
    }

    #pragma unroll
    for (int k = 0; k < QPT; k++) {
        const unsigned int key = enc_f(fminf(ma[k], mb[k]));
        atomicMin(&g_minenc[(dir * BB + b) * NN + nbase + k * TPB], key);
    }
}

// ---------------------------------------------------------------------------
// Kernel 3: decode mins, deferred sqrt, global sum -> loss_geo.
// ---------------------------------------------------------------------------
__global__ void __launch_bounds__(TPB) k_reduce(float* __restrict__ out)
{
    const int tid  = threadIdx.x;
    const int base = blockIdx.x * (QTOT / NRED_BLK) + tid;   // 1024 per block
    const float* __restrict__ hflat = &g_h[0][0][0];

    float s = 0.f;
    #pragma unroll
    for (int k = 0; k < 4; k++) {
        const int q = base + k * TPB;
        const float m = dec_f(g_minenc[q]);
        const float h = hflat[q];
        s += sqrtf(fmaxf(2.0f * (m + h), 0.0f));
    }

    float bs = block_reduce_sum(s);

    __shared__ bool is_last;
    if (tid == 0) {
        g_partials[blockIdx.x] = bs;
        __threadfence();
        is_last = (atomicAdd(&g_count, 1u) == NRED_BLK - 1);
    }
    __syncthreads();

    if (is_last) {
        const volatile float* vp = g_partials;
        float v = (tid < NRED_BLK) ? vp[tid] : 0.f;
        float tot = block_reduce_sum(v);
        if (tid == 0) {
            out[0] = tot * (1.0f / (BB * NN));
            g_count = 0;   // reset for next graph replay
        }
    }
}

// ---------------------------------------------------------------------------
extern "C" void kernel_launch(void* const* d_in, const int* in_sizes, int n_in,
                              void* d_out, int out_size)
{
    const float* pred_rot      = (const float*)d_in[0];
    const float* pred_trans    = (const float*)d_in[1];
    const float* ctx_hyp_rot   = (const float*)d_in[2];
    const float* ctx_hyp_trans = (const float*)d_in[3];
    const float* gt_rot        = (const float*)d_in[4];
    const float* gt_trans      = (const float*)d_in[5];
    const float* ctx_gt_rot    = (const float*)d_in[6];
    const float* ctx_gt_trans  = (const float*)d_in[7];
    const float* model_points  = (const float*)d_in[8];
    float* out = (float*)d_out;

    k_prep<<<(BB * NN) / TPB, TPB>>>(pred_rot, pred_trans,
                                     ctx_hyp_rot, ctx_hyp_trans,
                                     gt_rot, gt_trans,
                                     ctx_gt_rot, ctx_gt_trans,
                                     model_points, out);
    k_chamfer<<<dim3(NQCH, BB, 2 * NTCH), TPB>>>();
    k_reduce<<<NRED_BLK, TPB>>>(out);
}